// round 13
// baseline (speedup 1.0000x reference)
#include <cuda_runtime.h>
#include <cuda_bf16.h>
#include <cstdint>

// ============================================================================
// RelativeAttention (sm_103, TF32 HMMA, 16x(32x32) warps, A register-resident)
//
// out[bn,i=(h,w),j=(x,y)] = dot(q_i,k_j) + QW[bn,i, y-w+31] + QH[bn,i, x-h+31]
//
// K1 (convert_b): k -> tf32-rounded f32, chunk-XOR-swizzled K-major images
// K2 (attn_hmma): 544 thr = 16 worker warps (32x32 tiles) + 1 producer.
//   - stage q (linear) + ew/eh; exact fp32 qw/qh windows; A image in place
//   - A fragments preloaded ONCE into 64 regs/warp (no A smem traffic in loop)
//   - 8x 128x128 col-tiles, K=64; B via depth-3 32KB ring (producer 3 ahead)
//   - epilogue: smem qw/qh adds, STG.64
// ============================================================================

#define BNB 64
#define LQ  1024
#define DD  64
#define UNIT_BYTES 32768          // 128 cols x 64 K x f32 (tf32)

__device__ __align__(1024) unsigned char g_B[(size_t)512 * UNIT_BYTES];

typedef unsigned long long ull;

// ---------------- helpers ----------------
__device__ __forceinline__ void ffma2(ull& acc, ull a, ull b) {
    asm("fma.rn.f32x2 %0, %1, %2, %0;" : "+l"(acc) : "l"(a), "l"(b));
}
__device__ __forceinline__ void unpack2(ull v, float& lo, float& hi) {
    asm("mov.b64 {%0, %1}, %2;" : "=f"(lo), "=f"(hi) : "l"(v));
}
__device__ __forceinline__ float tf32r(float x) {
    float r; asm("cvt.rna.tf32.f32 %0, %1;" : "=f"(r) : "f"(x)); return r;
}
__device__ __forceinline__ uint32_t smem_u32(const void* p) {
    uint32_t a;
    asm("{ .reg .u64 t; cvta.to.shared.u64 t, %1; cvt.u32.u64 %0, t; }" : "=r"(a) : "l"(p));
    return a;
}
__device__ __forceinline__ uint32_t elect_one() {
    uint32_t p;
    asm volatile("{ .reg .pred p; elect.sync _|p, 0xFFFFFFFF; selp.b32 %0, 1, 0, p; }" : "=r"(p));
    return p;
}

#define MBAR_INIT(a, c) \
    asm volatile("mbarrier.init.shared.b64 [%0], %1;" :: "r"(a), "r"(c) : "memory")
#define MBAR_EXPECT_TX(a, b) \
    asm volatile("mbarrier.arrive.expect_tx.shared.b64 _, [%0], %1;" :: "r"(a), "r"(b) : "memory")
#define MBAR_ARRIVE(a) \
    asm volatile("mbarrier.arrive.shared.b64 _, [%0];" :: "r"(a) : "memory")
#define MBAR_WAIT(a, ph) do {                                                   \
    asm volatile("{\n\t.reg .pred P1;\n\t"                                      \
        "WL%=:\n\t"                                                             \
        "mbarrier.try_wait.parity.acquire.cta.shared::cta.b64 P1, [%0], %1, 0x989680;\n\t" \
        "@P1 bra.uni WD%=;\n\t bra.uni WL%=;\n\tWD%=:\n\t}"                      \
        :: "r"(a), "r"(ph) : "memory");                                          \
} while (0)

__device__ __forceinline__ void bulk_g2s(uint32_t dst, const void* src, uint32_t bytes, uint32_t mbar) {
    uint64_t gsrc = (uint64_t)__cvta_generic_to_global(src);
    asm volatile("cp.async.bulk.shared::cta.global.mbarrier::complete_tx::bytes [%0], [%1], %2, [%3];"
                 :: "r"(dst), "l"(gsrc), "r"(bytes), "r"(mbar) : "memory");
}

__device__ __forceinline__ void ldsm4(uint32_t& r0, uint32_t& r1, uint32_t& r2, uint32_t& r3,
                                      uint32_t addr) {
    asm volatile("ldmatrix.sync.aligned.m8n8.x4.shared.b16 {%0,%1,%2,%3}, [%4];"
                 : "=r"(r0), "=r"(r1), "=r"(r2), "=r"(r3) : "r"(addr));
}
__device__ __forceinline__ void mma_tf32(float* c, const uint32_t* a, const uint32_t* b) {
    asm volatile("mma.sync.aligned.m16n8k8.row.col.f32.tf32.tf32.f32 "
                 "{%0,%1,%2,%3}, {%4,%5,%6,%7}, {%8,%9}, {%0,%1,%2,%3};"
                 : "+f"(c[0]), "+f"(c[1]), "+f"(c[2]), "+f"(c[3])
                 : "r"(a[0]), "r"(a[1]), "r"(a[2]), "r"(a[3]), "r"(b[0]), "r"(b[1]));
}

// image layout: 128 rows x 256B; 16B chunk c at row r lands at chunk (c ^ (r&7))
__device__ __forceinline__ uint32_t img_off(int row, int chunk) {
    return (uint32_t)row * 256u + (uint32_t)((chunk ^ (row & 7)) * 16);
}

// ----------------------------------------------------------------------------
// Kernel 1: convert k -> tf32 swizzled K-major images (32KB per 128-col tile)
// ----------------------------------------------------------------------------
__global__ __launch_bounds__(256) void convert_b_kernel(const float* __restrict__ k)
{
    int unit = blockIdx.x;
    const float* base = k + (size_t)unit * 128 * DD;
    unsigned char* dst = g_B + (size_t)unit * UNIT_BYTES;
    int tid = threadIdx.x;

    #pragma unroll
    for (int c = 0; c < 4; c++) {
        int chunk = tid + c * 256;          // 0..1023
        int row = chunk >> 3;
        int d0  = (chunk & 7) * 8;
        float4 v0 = *(const float4*)&base[row * DD + d0];
        float4 v1 = *(const float4*)&base[row * DD + d0 + 4];
        float4 o0 = make_float4(tf32r(v0.x), tf32r(v0.y), tf32r(v0.z), tf32r(v0.w));
        float4 o1 = make_float4(tf32r(v1.x), tf32r(v1.y), tf32r(v1.z), tf32r(v1.w));
        *(float4*)(dst + img_off(row, (d0 >> 2)))     = o0;
        *(float4*)(dst + img_off(row, (d0 >> 2) + 1)) = o1;
    }
}

// ----------------------------------------------------------------------------
// Kernel 2: fused tables + A-convert + TF32 HMMA GEMM + epilogue
// ----------------------------------------------------------------------------
// byte offsets
#define AS_OFF   0                     // A image 32KB (pre-GEMM: q fp32 linear)
#define BS_OFF   32768                 // 3 x 32KB B ring (pre-GEMM: ew/eh stage)
#define QW_OFF   131072                // 128 x pitch40 f32 = 20480
#define QH_OFF   151552                // 128 x pitch33 f32 = 16896
#define CTRL_OFF 168448                // 6 mbarriers
#define SMEM_SZ  168512
// float-index offsets for ew/eh staging inside the B-ring region
#define EWF  (BS_OFF / 4)              // ew: 63 rows x pitch66 (float2 stores)
#define EHF  (EWF + 4160)              // eh: 63 rows x pitch66

#define NTHR 544                       // 16 workers + 1 producer

__global__ __launch_bounds__(NTHR, 1) void attn_hmma_kernel(
    const float* __restrict__ q, const float* __restrict__ ew,
    const float* __restrict__ eh, float* __restrict__ out)
{
    extern __shared__ unsigned char smem[];
    float* smem_f = (float*)smem;
    const uint32_t sb = smem_u32(smem);

    const int bn = blockIdx.x >> 3;
    const int rt = blockIdx.x & 7;
    const int row0 = rt * 128;
    const int n_head = bn & 7;
    const int tid = threadIdx.x, lane = tid & 31, warp = tid >> 5;
    const int rgroup = warp >> 2;     // workers: 0..3 -> 32-row group
    const int cstrip = warp & 3;      // workers: 0..3 -> 32-col strip

    const uint32_t mbF = sb + CTRL_OFF;        // full[3], count 1
    const uint32_t mcF = sb + CTRL_OFF + 24;   // consumed[3], count 16
    if (tid == 0) {
        #pragma unroll
        for (int i = 0; i < 3; i++) { MBAR_INIT(mbF + i * 8, 1); MBAR_INIT(mcF + i * 8, 16); }
    }

    // ---- phase A: stage q (linear, A region) + ew/eh (pitch 66, B region) ----
    if (tid < 512) {
        const float* ewb = ew + (size_t)n_head * 63 * DD;
        const float* ehb = eh + (size_t)n_head * 63 * DD;
        for (int c = tid; c < 1008; c += 512) {          // 63 rows x 16 float4
            int row = c >> 4, d0 = (c & 15) * 4;
            float4 vw = *(const float4*)&ewb[row * DD + d0];
            float4 vh = *(const float4*)&ehb[row * DD + d0];
            float* dw = &smem_f[EWF + row * 66 + d0];
            float* dh = &smem_f[EHF + row * 66 + d0];
            *(float2*)(dw + 0) = make_float2(vw.x, vw.y);
            *(float2*)(dw + 2) = make_float2(vw.z, vw.w);
            *(float2*)(dh + 0) = make_float2(vh.x, vh.y);
            *(float2*)(dh + 2) = make_float2(vh.z, vh.w);
        }
        const float* qb = q + ((size_t)bn * LQ + row0) * DD;
        #pragma unroll
        for (int it = 0; it < 4; it++) {                 // 128 rows x 16 float4
            int c = tid + it * 512;
            int row = c >> 4, d0 = (c & 15) * 4;
            *(float4*)&smem_f[row * 64 + d0] = *(const float4*)&qb[(size_t)row * DD + d0];
        }
    }
    __syncthreads();   // S1

    // ---- phase B: exact fp32 qw/qh windows + qreg read ----
    float* qw_s = smem_f + QW_OFF / 4;   // [row][y] pitch 40
    float* qh_s = smem_f + QH_OFF / 4;   // [row][x] pitch 33
    if (warp < 16) {
        #pragma unroll 1
        for (int pass = 0; pass < 16; pass++) {
            int task = warp * 16 + pass;                  // 0..255
            bool isW = task < 128;
            int r = isW ? task : task - 128;
            int shift = isW ? (31 - (r & 31)) : (31 - (rt * 4 + (r >> 5)));
            const float* erow = smem_f + (isW ? EWF : EHF) + (size_t)(shift + lane) * 66;
            const float* qrow = smem_f + (size_t)r * 64;
            ull acc = 0;
            #pragma unroll 8
            for (int kk = 0; kk < 32; kk++) {
                ull qp = *(const ull*)(qrow + 2 * kk);    // broadcast
                ull ep = *(const ull*)(erow + 2 * kk);
                ffma2(acc, qp, ep);
            }
            float vlo, vhi; unpack2(acc, vlo, vhi);
            float v = vlo + vhi;
            if (isW) qw_s[r * 40 + lane] = v;
            else     qh_s[r * 33 + lane] = v;
        }
    }
    // read q chunks this thread will rewrite swizzled
    float qreg[2][8];
    if (tid < 512) {
        #pragma unroll
        for (int c = 0; c < 2; c++) {
            int chunk = tid + c * 512;
            int row = chunk >> 3, d0 = (chunk & 7) * 8;
            float4 v0 = *(const float4*)&smem_f[row * 64 + d0];
            float4 v1 = *(const float4*)&smem_f[row * 64 + d0 + 4];
            qreg[c][0] = v0.x; qreg[c][1] = v0.y; qreg[c][2] = v0.z; qreg[c][3] = v0.w;
            qreg[c][4] = v1.x; qreg[c][5] = v1.y; qreg[c][6] = v1.z; qreg[c][7] = v1.w;
        }
    }
    __syncthreads();   // S2: q/e reads done; tables written; B ring region free

    // producer prologue: fill all 3 ring slots (overlaps phase C below)
    if (warp == 16 && elect_one()) {
        asm volatile("fence.proxy.async.shared::cta;" ::: "memory");
        #pragma unroll
        for (int t = 0; t < 3; t++) {
            MBAR_EXPECT_TX(mbF + t * 8, UNIT_BYTES);
            bulk_g2s(sb + BS_OFF + t * UNIT_BYTES,
                     g_B + ((size_t)bn * 8 + t) * UNIT_BYTES, UNIT_BYTES, mbF + t * 8);
        }
    }

    // ---- phase C: write swizzled tf32 A image in place ----
    if (tid < 512) {
        #pragma unroll
        for (int c = 0; c < 2; c++) {
            int chunk = tid + c * 512;
            int row = chunk >> 3, d0 = (chunk & 7) * 8;
            float4 o0 = make_float4(tf32r(qreg[c][0]), tf32r(qreg[c][1]),
                                    tf32r(qreg[c][2]), tf32r(qreg[c][3]));
            float4 o1 = make_float4(tf32r(qreg[c][4]), tf32r(qreg[c][5]),
                                    tf32r(qreg[c][6]), tf32r(qreg[c][7]));
            *(float4*)(smem + AS_OFF + img_off(row, (d0 >> 2)))     = o0;
            *(float4*)(smem + AS_OFF + img_off(row, (d0 >> 2) + 1)) = o1;
        }
    }
    __syncthreads();   // S3: A image ready

    // lane decomposition for ldmatrix addressing (f32 8x4 blocks as b16 m8n8)
    const int r8 = lane & 7;
    const int ma = (lane >> 3) & 1, ka = lane >> 4;       // A: row-half, chunk-half
    const int gb = lane >> 4,       cb = (lane >> 3) & 1; // B: n-group, chunk-half
    const uint32_t a_base = sb + AS_OFF + (uint32_t)(rgroup * 32 + ma * 8 + r8) * 256;
    const uint32_t b_off  = (uint32_t)(cstrip * 32 + gb * 8 + r8) * 256;

    // epilogue lane mapping
    const int l4 = lane >> 2, l2 = (lane & 3) * 2;
    float* outb = out + ((size_t)bn << 20);

    if (warp < 16) {
        // ---- preload ALL A fragments (identical for every col-tile): 64 regs ----
        uint32_t afr[8][2][4];                 // [s][mt][4]
        #pragma unroll
        for (int s = 0; s < 8; s++) {
            const uint32_t ca = (uint32_t)(((2 * s + ka) ^ r8) * 16);
            #pragma unroll
            for (int mt = 0; mt < 2; mt++)
                ldsm4(afr[s][mt][0], afr[s][mt][1], afr[s][mt][2], afr[s][mt][3],
                      a_base + (uint32_t)(mt * 16 * 256) + ca);
        }

        int wbuf = 0, wph = 0;
        #pragma unroll 1
        for (int ct = 0; ct < 8; ct++) {
            MBAR_WAIT(mbF + wbuf * 8, wph);
            const uint32_t b_base = sb + BS_OFF + (uint32_t)wbuf * UNIT_BYTES + b_off;

            float acc[2][4][4];
            #pragma unroll
            for (int mt = 0; mt < 2; mt++)
                #pragma unroll
                for (int nn = 0; nn < 4; nn++)
                    #pragma unroll
                    for (int e = 0; e < 4; e++) acc[mt][nn][e] = 0.f;

            #pragma unroll
            for (int s = 0; s < 8; s++) {
                uint32_t bf[2][4];
                const uint32_t cbb = (uint32_t)(((2 * s + cb) ^ r8) * 16);
                #pragma unroll
                for (int np = 0; np < 2; np++)
                    ldsm4(bf[np][0], bf[np][1], bf[np][2], bf[np][3],
                          b_base + (uint32_t)(np * 16 * 256) + cbb);
                #pragma unroll
                for (int mt = 0; mt < 2; mt++)
                    #pragma unroll
                    for (int nn = 0; nn < 4; nn++)
                        mma_tf32(acc[mt][nn], afr[s][mt], &bf[nn >> 1][(nn & 1) * 2]);
            }

            // all B ldsm of this tile complete -> release the ring slot
            if (elect_one()) MBAR_ARRIVE(mcF + wbuf * 8);
            if (++wbuf == 3) { wbuf = 0; wph ^= 1; }

            // epilogue (overlaps other warps' MMA; no CTA barrier)
            const int xq = ct * 4 + cstrip;               // warp-uniform x index
            #pragma unroll
            for (int mt = 0; mt < 2; mt++) {
                #pragma unroll
                for (int half = 0; half < 2; half++) {
                    const int r = rgroup * 32 + mt * 16 + half * 8 + l4;
                    const float hv = qh_s[r * 33 + xq];
                    float* op = outb + (size_t)(row0 + r) * 1024
                              + ct * 128 + cstrip * 32 + l2;
                    #pragma unroll
                    for (int nn = 0; nn < 4; nn++) {
                        float2 wv = *(const float2*)&qw_s[r * 40 + nn * 8 + l2];
                        float2 o;
                        o.x = acc[mt][nn][half * 2 + 0] + wv.x + hv;
                        o.y = acc[mt][nn][half * 2 + 1] + wv.y + hv;
                        *(float2*)(op + nn * 8) = o;
                    }
                }
            }
        }
    } else if (warp == 16) {
        // ---- producer: tiles 3..7 through the ring (3 ahead) ----
        if (elect_one()) {
            int pbuf = 0, pph = 0;
            #pragma unroll 1
            for (int t = 3; t < 8; t++) {
                MBAR_WAIT(mcF + pbuf * 8, pph);
                MBAR_EXPECT_TX(mbF + pbuf * 8, UNIT_BYTES);
                bulk_g2s(sb + BS_OFF + (uint32_t)pbuf * UNIT_BYTES,
                         g_B + ((size_t)bn * 8 + t) * UNIT_BYTES, UNIT_BYTES,
                         mbF + pbuf * 8);
                if (++pbuf == 3) { pbuf = 0; pph ^= 1; }
            }
        }
    }
}

// ----------------------------------------------------------------------------
extern "C" void kernel_launch(void* const* d_in, const int* in_sizes, int n_in,
                              void* d_out, int out_size)
{
    const float* q  = (const float*)d_in[0];
    const float* k  = (const float*)d_in[1];
    const float* ew = (const float*)d_in[2];
    const float* eh = (const float*)d_in[3];
    float* out = (float*)d_out;

    cudaFuncSetAttribute(attn_hmma_kernel, cudaFuncAttributeMaxDynamicSharedMemorySize, SMEM_SZ);

    convert_b_kernel<<<512, 256>>>(k);
    attn_hmma_kernel<<<512, NTHR, SMEM_SZ>>>(q, ew, eh, out);
}

// round 14
// speedup vs baseline: 1.1473x; 1.1473x over previous
#include <cuda_runtime.h>
#include <cuda_bf16.h>
#include <cstdint>

// ============================================================================
// RelativeAttention (sm_103, TF32 HMMA, R9 base + pipelined frags + staged STG)
//
// out[bn,i=(h,w),j=(x,y)] = dot(q_i,k_j) + QW[bn,i, y-w+31] + QH[bn,i, x-h+31]
//
// K1 (convert_b): k -> tf32-rounded f32, chunk-XOR-swizzled K-major images
// K2 (attn_hmma): 288 thr = 8 workers (64x32 tiles) + 1 producer.
//   - stage q (linear) + ew/eh; exact fp32 qw/qh windows; A image in place
//   - 8x 128x128 col-tiles, K=64; B double-buffered via producer cp.async.bulk
//   - mainloop: A/B fragments explicitly double-buffered across k-steps
//   - epilogue: tables added in regs, staged to warp-private smem (pitch 40),
//     re-read as LDS.128, coalesced STG.128 (4 full lines per instr)
// ============================================================================

#define BNB 64
#define LQ  1024
#define DD  64
#define UNIT_BYTES 32768          // 128 cols x 64 K x f32 (tf32)

__device__ __align__(1024) unsigned char g_B[(size_t)512 * UNIT_BYTES];

typedef unsigned long long ull;

// ---------------- helpers ----------------
__device__ __forceinline__ void ffma2(ull& acc, ull a, ull b) {
    asm("fma.rn.f32x2 %0, %1, %2, %0;" : "+l"(acc) : "l"(a), "l"(b));
}
__device__ __forceinline__ void unpack2(ull v, float& lo, float& hi) {
    asm("mov.b64 {%0, %1}, %2;" : "=f"(lo), "=f"(hi) : "l"(v));
}
__device__ __forceinline__ float tf32r(float x) {
    float r; asm("cvt.rna.tf32.f32 %0, %1;" : "=f"(r) : "f"(x)); return r;
}
__device__ __forceinline__ uint32_t smem_u32(const void* p) {
    uint32_t a;
    asm("{ .reg .u64 t; cvta.to.shared.u64 t, %1; cvt.u32.u64 %0, t; }" : "=r"(a) : "l"(p));
    return a;
}
__device__ __forceinline__ uint32_t elect_one() {
    uint32_t p;
    asm volatile("{ .reg .pred p; elect.sync _|p, 0xFFFFFFFF; selp.b32 %0, 1, 0, p; }" : "=r"(p));
    return p;
}

#define MBAR_INIT(a, c) \
    asm volatile("mbarrier.init.shared.b64 [%0], %1;" :: "r"(a), "r"(c) : "memory")
#define MBAR_EXPECT_TX(a, b) \
    asm volatile("mbarrier.arrive.expect_tx.shared.b64 _, [%0], %1;" :: "r"(a), "r"(b) : "memory")
#define MBAR_ARRIVE(a) \
    asm volatile("mbarrier.arrive.shared.b64 _, [%0];" :: "r"(a) : "memory")
#define MBAR_WAIT(a, ph) do {                                                   \
    asm volatile("{\n\t.reg .pred P1;\n\t"                                      \
        "WL%=:\n\t"                                                             \
        "mbarrier.try_wait.parity.acquire.cta.shared::cta.b64 P1, [%0], %1, 0x989680;\n\t" \
        "@P1 bra.uni WD%=;\n\t bra.uni WL%=;\n\tWD%=:\n\t}"                      \
        :: "r"(a), "r"(ph) : "memory");                                          \
} while (0)

__device__ __forceinline__ void bulk_g2s(uint32_t dst, const void* src, uint32_t bytes, uint32_t mbar) {
    uint64_t gsrc = (uint64_t)__cvta_generic_to_global(src);
    asm volatile("cp.async.bulk.shared::cta.global.mbarrier::complete_tx::bytes [%0], [%1], %2, [%3];"
                 :: "r"(dst), "l"(gsrc), "r"(bytes), "r"(mbar) : "memory");
}

__device__ __forceinline__ void ldsm4(uint32_t& r0, uint32_t& r1, uint32_t& r2, uint32_t& r3,
                                      uint32_t addr) {
    asm volatile("ldmatrix.sync.aligned.m8n8.x4.shared.b16 {%0,%1,%2,%3}, [%4];"
                 : "=r"(r0), "=r"(r1), "=r"(r2), "=r"(r3) : "r"(addr));
}
__device__ __forceinline__ void mma_tf32(float* c, const uint32_t* a, const uint32_t* b) {
    asm volatile("mma.sync.aligned.m16n8k8.row.col.f32.tf32.tf32.f32 "
                 "{%0,%1,%2,%3}, {%4,%5,%6,%7}, {%8,%9}, {%0,%1,%2,%3};"
                 : "+f"(c[0]), "+f"(c[1]), "+f"(c[2]), "+f"(c[3])
                 : "r"(a[0]), "r"(a[1]), "r"(a[2]), "r"(a[3]), "r"(b[0]), "r"(b[1]));
}

// image layout: 128 rows x 256B; 16B chunk c at row r lands at chunk (c ^ (r&7))
__device__ __forceinline__ uint32_t img_off(int row, int chunk) {
    return (uint32_t)row * 256u + (uint32_t)((chunk ^ (row & 7)) * 16);
}

// ----------------------------------------------------------------------------
// Kernel 1: convert k -> tf32 swizzled K-major images (32KB per 128-col tile)
// ----------------------------------------------------------------------------
__global__ __launch_bounds__(256) void convert_b_kernel(const float* __restrict__ k)
{
    int unit = blockIdx.x;
    const float* base = k + (size_t)unit * 128 * DD;
    unsigned char* dst = g_B + (size_t)unit * UNIT_BYTES;
    int tid = threadIdx.x;

    #pragma unroll
    for (int c = 0; c < 4; c++) {
        int chunk = tid + c * 256;          // 0..1023
        int row = chunk >> 3;
        int d0  = (chunk & 7) * 8;
        float4 v0 = *(const float4*)&base[row * DD + d0];
        float4 v1 = *(const float4*)&base[row * DD + d0 + 4];
        float4 o0 = make_float4(tf32r(v0.x), tf32r(v0.y), tf32r(v0.z), tf32r(v0.w));
        float4 o1 = make_float4(tf32r(v1.x), tf32r(v1.y), tf32r(v1.z), tf32r(v1.w));
        *(float4*)(dst + img_off(row, (d0 >> 2)))     = o0;
        *(float4*)(dst + img_off(row, (d0 >> 2) + 1)) = o1;
    }
}

// ----------------------------------------------------------------------------
// Kernel 2: fused tables + A-convert + TF32 HMMA GEMM + staged epilogue
// ----------------------------------------------------------------------------
// byte offsets
#define AS_OFF   0                     // A image 32KB (pre-GEMM: q fp32 linear)
#define BS_OFF   32768                 // two 32KB B buffers (pre-GEMM: ew/eh)
#define QW_OFF   98304                 // 128 x pitch40 f32 = 20480
#define QH_OFF   118784                // 128 x pitch33 f32 = 16896
#define STG_OFF  135680                // 8 warps x 64 rows x pitch40 f32 = 81920
#define CTRL_OFF 217600                // 4 mbarriers
#define SMEM_SZ  217664
// float-index offsets for ew/eh staging inside the B-buffer region
#define EWF  (BS_OFF / 4)              // ew: 63 rows x pitch66 (float2 stores)
#define EHF  (EWF + 4160)              // eh: 63 rows x pitch66

__global__ __launch_bounds__(288, 1) void attn_hmma_kernel(
    const float* __restrict__ q, const float* __restrict__ ew,
    const float* __restrict__ eh, float* __restrict__ out)
{
    extern __shared__ unsigned char smem[];
    float* smem_f = (float*)smem;
    const uint32_t sb = smem_u32(smem);

    const int bn = blockIdx.x >> 3;
    const int rt = blockIdx.x & 7;
    const int row0 = rt * 128;
    const int n_head = bn & 7;
    const int tid = threadIdx.x, lane = tid & 31, warp = tid >> 5;
    const int warp_r = warp >> 2;     // workers: 0..1 -> 64-row half
    const int warp_c = warp & 3;      // workers: 0..3 -> 32-col strip

    const uint32_t mb0 = sb + CTRL_OFF,      mb1 = mb0 + 8;   // B-full (count 1)
    const uint32_t mc0 = mb0 + 16,           mc1 = mb0 + 24;  // B-consumed (count 8)
    if (tid == 0) {
        MBAR_INIT(mb0, 1); MBAR_INIT(mb1, 1);
        MBAR_INIT(mc0, 8); MBAR_INIT(mc1, 8);
    }

    // ---- phase A: stage q (linear, A region) + ew/eh (pitch 66, B region) ----
    if (tid < 256) {
        const float* ewb = ew + (size_t)n_head * 63 * DD;
        const float* ehb = eh + (size_t)n_head * 63 * DD;
        for (int c = tid; c < 1008; c += 256) {          // 63 rows x 16 float4
            int row = c >> 4, d0 = (c & 15) * 4;
            float4 vw = *(const float4*)&ewb[row * DD + d0];
            float4 vh = *(const float4*)&ehb[row * DD + d0];
            float* dw = &smem_f[EWF + row * 66 + d0];
            float* dh = &smem_f[EHF + row * 66 + d0];
            *(float2*)(dw + 0) = make_float2(vw.x, vw.y);
            *(float2*)(dw + 2) = make_float2(vw.z, vw.w);
            *(float2*)(dh + 0) = make_float2(vh.x, vh.y);
            *(float2*)(dh + 2) = make_float2(vh.z, vh.w);
        }
        const float* qb = q + ((size_t)bn * LQ + row0) * DD;
        #pragma unroll
        for (int it = 0; it < 8; it++) {                 // 128 rows x 16 float4
            int c = tid + it * 256;
            int row = c >> 4, d0 = (c & 15) * 4;
            *(float4*)&smem_f[row * 64 + d0] = *(const float4*)&qb[(size_t)row * DD + d0];
        }
    }
    __syncthreads();   // S1

    // ---- phase B: exact fp32 qw/qh windows + qreg read ----
    float* qw_s = smem_f + QW_OFF / 4;   // [row][y] pitch 40
    float* qh_s = smem_f + QH_OFF / 4;   // [row][x] pitch 33
    if (warp < 8) {
        #pragma unroll 1
        for (int pass = 0; pass < 32; pass++) {
            int task = warp * 32 + pass;
            bool isW = task < 128;
            int r = isW ? task : task - 128;
            int shift = isW ? (31 - (r & 31)) : (31 - (rt * 4 + (r >> 5)));
            const float* erow = smem_f + (isW ? EWF : EHF) + (size_t)(shift + lane) * 66;
            const float* qrow = smem_f + (size_t)r * 64;
            ull acc = 0;
            #pragma unroll 8
            for (int kk = 0; kk < 32; kk++) {
                ull qp = *(const ull*)(qrow + 2 * kk);    // broadcast
                ull ep = *(const ull*)(erow + 2 * kk);
                ffma2(acc, qp, ep);
            }
            float vlo, vhi; unpack2(acc, vlo, vhi);
            float v = vlo + vhi;
            if (isW) qw_s[r * 40 + lane] = v;
            else     qh_s[r * 33 + lane] = v;
        }
    }
    // read q chunks this thread will rewrite swizzled
    float qreg[4][8];
    if (tid < 256) {
        #pragma unroll
        for (int c = 0; c < 4; c++) {
            int chunk = tid + c * 256;
            int row = chunk >> 3, d0 = (chunk & 7) * 8;
            float4 v0 = *(const float4*)&smem_f[row * 64 + d0];
            float4 v1 = *(const float4*)&smem_f[row * 64 + d0 + 4];
            qreg[c][0] = v0.x; qreg[c][1] = v0.y; qreg[c][2] = v0.z; qreg[c][3] = v0.w;
            qreg[c][4] = v1.x; qreg[c][5] = v1.y; qreg[c][6] = v1.z; qreg[c][7] = v1.w;
        }
    }
    __syncthreads();   // S2: q/e reads done; tables written; B region free

    // producer prologue: fill both B buffers (overlaps phase C below)
    if (warp == 8 && elect_one()) {
        asm volatile("fence.proxy.async.shared::cta;" ::: "memory");
        MBAR_EXPECT_TX(mb0, UNIT_BYTES);
        bulk_g2s(sb + BS_OFF, g_B + (size_t)(bn * 8) * UNIT_BYTES, UNIT_BYTES, mb0);
        MBAR_EXPECT_TX(mb1, UNIT_BYTES);
        bulk_g2s(sb + BS_OFF + UNIT_BYTES, g_B + (size_t)(bn * 8 + 1) * UNIT_BYTES,
                 UNIT_BYTES, mb1);
    }

    // ---- phase C: write swizzled tf32 A image in place ----
    if (tid < 256) {
        #pragma unroll
        for (int c = 0; c < 4; c++) {
            int chunk = tid + c * 256;
            int row = chunk >> 3, d0 = (chunk & 7) * 8;
            float4 o0 = make_float4(tf32r(qreg[c][0]), tf32r(qreg[c][1]),
                                    tf32r(qreg[c][2]), tf32r(qreg[c][3]));
            float4 o1 = make_float4(tf32r(qreg[c][4]), tf32r(qreg[c][5]),
                                    tf32r(qreg[c][6]), tf32r(qreg[c][7]));
            *(float4*)(smem + AS_OFF + img_off(row, (d0 >> 2)))     = o0;
            *(float4*)(smem + AS_OFF + img_off(row, (d0 >> 2) + 1)) = o1;
        }
    }
    __syncthreads();   // S3: A image ready

    // lane decomposition for ldmatrix addressing (f32 8x4 blocks as b16 m8n8)
    const int r8 = lane & 7;
    const int ma = (lane >> 3) & 1, ka = lane >> 4;       // A: row-half, chunk-half
    const int gb = lane >> 4,       cb = (lane >> 3) & 1; // B: n-group, chunk-half
    const uint32_t a_base = sb + AS_OFF + (uint32_t)(warp_r * 64 + ma * 8 + r8) * 256;
    const uint32_t b_off  = (uint32_t)(warp_c * 32 + gb * 8 + r8) * 256;

    // epilogue lane mapping
    const int l4 = lane >> 2, l2 = (lane & 3) * 2;
    float* outb = out + ((size_t)bn << 20);
    float* stg  = smem_f + STG_OFF / 4 + warp * 2560;     // warp-private 64 x pitch40

    if (warp < 8) {
        #pragma unroll 1
        for (int ct = 0; ct < 8; ct++) {
            const int buf = ct & 1;
            MBAR_WAIT(buf ? mb1 : mb0, (ct >> 1) & 1);
            const uint32_t b_base = sb + BS_OFF + (uint32_t)buf * UNIT_BYTES + b_off;

            float acc[4][4][4];
            #pragma unroll
            for (int mt = 0; mt < 4; mt++)
                #pragma unroll
                for (int nn = 0; nn < 4; nn++)
                    #pragma unroll
                    for (int e = 0; e < 4; e++) acc[mt][nn][e] = 0.f;

            // fragment double buffers (software pipeline across k-steps)
            uint32_t af[2][4][4], bf[2][2][4];
            {
                const uint32_t ca = (uint32_t)((ka ^ r8) * 16);
                #pragma unroll
                for (int mt = 0; mt < 4; mt++)
                    ldsm4(af[0][mt][0], af[0][mt][1], af[0][mt][2], af[0][mt][3],
                          a_base + (uint32_t)(mt * 16 * 256) + ca);
                const uint32_t cbb = (uint32_t)((cb ^ r8) * 16);
                #pragma unroll
                for (int np = 0; np < 2; np++)
                    ldsm4(bf[0][np][0], bf[0][np][1], bf[0][np][2], bf[0][np][3],
                          b_base + (uint32_t)(np * 16 * 256) + cbb);
            }

            #pragma unroll
            for (int s = 0; s < 8; s++) {
                const int cur = s & 1, nxt = cur ^ 1;
                if (s < 7) {   // prefetch next k-step's fragments
                    const uint32_t ca = (uint32_t)(((2 * (s + 1) + ka) ^ r8) * 16);
                    #pragma unroll
                    for (int mt = 0; mt < 4; mt++)
                        ldsm4(af[nxt][mt][0], af[nxt][mt][1], af[nxt][mt][2], af[nxt][mt][3],
                              a_base + (uint32_t)(mt * 16 * 256) + ca);
                    const uint32_t cbb = (uint32_t)(((2 * (s + 1) + cb) ^ r8) * 16);
                    #pragma unroll
                    for (int np = 0; np < 2; np++)
                        ldsm4(bf[nxt][np][0], bf[nxt][np][1], bf[nxt][np][2], bf[nxt][np][3],
                              b_base + (uint32_t)(np * 16 * 256) + cbb);
                }
                #pragma unroll
                for (int mt = 0; mt < 4; mt++)
                    #pragma unroll
                    for (int nn = 0; nn < 4; nn++)
                        mma_tf32(acc[mt][nn], af[cur][mt], &bf[cur][nn >> 1][(nn & 1) * 2]);
            }

            // all B ldsm of this tile complete -> release the buffer
            if (elect_one()) MBAR_ARRIVE(buf ? mc1 : mc0);

            // ---- staged epilogue (warp-private; no CTA barrier) ----
            const int xq = ct * 4 + warp_c;               // warp-uniform x index
            #pragma unroll
            for (int mt = 0; mt < 4; mt++) {
                #pragma unroll
                for (int half = 0; half < 2; half++) {
                    const int lr = mt * 16 + half * 8 + l4;       // local row 0..63
                    const int r  = warp_r * 64 + lr;
                    const float hv = qh_s[r * 33 + xq];
                    #pragma unroll
                    for (int nn = 0; nn < 4; nn++) {
                        float2 wv = *(const float2*)&qw_s[r * 40 + nn * 8 + l2];
                        float2 o;
                        o.x = acc[mt][nn][half * 2 + 0] + wv.x + hv;
                        o.y = acc[mt][nn][half * 2 + 1] + wv.y + hv;
                        *(float2*)&stg[lr * 40 + nn * 8 + l2] = o;  // conflict-free
                    }
                }
            }
            __syncwarp();

            // coalesced writeout: 4 rows x 128B per STG.128
            {
                const int rg = lane >> 3, c4 = (lane & 7) * 4;
                float* opb = outb + (size_t)(row0 + warp_r * 64) * 1024
                           + ct * 128 + warp_c * 32;
                #pragma unroll
                for (int rr = 0; rr < 16; rr++) {
                    const int lr = rr * 4 + rg;
                    float4 v = *(const float4*)&stg[lr * 40 + c4];
                    *(float4*)&opb[(size_t)lr * 1024 + c4] = v;
                }
            }
            __syncwarp();
        }
    } else if (warp == 8) {
        // ---- producer: tiles 2..7 (double buffer, waits consumed[t-2]) ----
        if (elect_one()) {
            #pragma unroll 1
            for (int t = 2; t < 8; t++) {
                const int b = t & 1;
                MBAR_WAIT(b ? mc1 : mc0, ((t - 2) >> 1) & 1);
                MBAR_EXPECT_TX(b ? mb1 : mb0, UNIT_BYTES);
                bulk_g2s(sb + BS_OFF + (uint32_t)b * UNIT_BYTES,
                         g_B + ((size_t)bn * 8 + t) * UNIT_BYTES, UNIT_BYTES,
                         b ? mb1 : mb0);
            }
        }
    }
}

// ----------------------------------------------------------------------------
extern "C" void kernel_launch(void* const* d_in, const int* in_sizes, int n_in,
                              void* d_out, int out_size)
{
    const float* q  = (const float*)d_in[0];
    const float* k  = (const float*)d_in[1];
    const float* ew = (const float*)d_in[2];
    const float* eh = (const float*)d_in[3];
    float* out = (float*)d_out;

    cudaFuncSetAttribute(attn_hmma_kernel, cudaFuncAttributeMaxDynamicSharedMemorySize, SMEM_SZ);

    convert_b_kernel<<<512, 256>>>(k);
    attn_hmma_kernel<<<512, 288, SMEM_SZ>>>(q, ew, eh, out);
}

// round 15
// speedup vs baseline: 1.3118x; 1.1434x over previous
#include <cuda_runtime.h>
#include <cuda_bf16.h>
#include <cstdint>

// ============================================================================
// RelativeAttention (sm_103, TF32 HMMA, R9 pipeline at 64-row CTAs, 2 CTAs/SM)
//
// out[bn,i=(h,w),j=(x,y)] = dot(q_i,k_j) + QW[bn,i, y-w+31] + QH[bn,i, x-h+31]
//
// K1 (convert_b): k -> tf32-rounded f32, chunk-XOR-swizzled K-major images
// K2 (attn_hmma): grid 1024 = (bn, 16 row-tiles of 64). 288 thr =
//   8 workers (32x32 warp tiles) + 1 producer. Same coarse pipeline as R9:
//   full-K 32KB B units, depth-2 ring, 8 waits/CTA, direct STG.64 epilogue.
//   Halved per-CTA footprint -> 98.3KB smem, ~96 regs -> 2 CTAs/SM (18 warps).
// ============================================================================

#define BNB 64
#define LQ  1024
#define DD  64
#define UNIT_BYTES 32768          // 128 cols x 64 K x f32 (tf32)

__device__ __align__(1024) unsigned char g_B[(size_t)512 * UNIT_BYTES];

typedef unsigned long long ull;

// ---------------- helpers ----------------
__device__ __forceinline__ void ffma2(ull& acc, ull a, ull b) {
    asm("fma.rn.f32x2 %0, %1, %2, %0;" : "+l"(acc) : "l"(a), "l"(b));
}
__device__ __forceinline__ void unpack2(ull v, float& lo, float& hi) {
    asm("mov.b64 {%0, %1}, %2;" : "=f"(lo), "=f"(hi) : "l"(v));
}
__device__ __forceinline__ float tf32r(float x) {
    float r; asm("cvt.rna.tf32.f32 %0, %1;" : "=f"(r) : "f"(x)); return r;
}
__device__ __forceinline__ uint32_t smem_u32(const void* p) {
    uint32_t a;
    asm("{ .reg .u64 t; cvta.to.shared.u64 t, %1; cvt.u32.u64 %0, t; }" : "=r"(a) : "l"(p));
    return a;
}
__device__ __forceinline__ uint32_t elect_one() {
    uint32_t p;
    asm volatile("{ .reg .pred p; elect.sync _|p, 0xFFFFFFFF; selp.b32 %0, 1, 0, p; }" : "=r"(p));
    return p;
}

#define MBAR_INIT(a, c) \
    asm volatile("mbarrier.init.shared.b64 [%0], %1;" :: "r"(a), "r"(c) : "memory")
#define MBAR_EXPECT_TX(a, b) \
    asm volatile("mbarrier.arrive.expect_tx.shared.b64 _, [%0], %1;" :: "r"(a), "r"(b) : "memory")
#define MBAR_ARRIVE(a) \
    asm volatile("mbarrier.arrive.shared.b64 _, [%0];" :: "r"(a) : "memory")
#define MBAR_WAIT(a, ph) do {                                                   \
    asm volatile("{\n\t.reg .pred P1;\n\t"                                      \
        "WL%=:\n\t"                                                             \
        "mbarrier.try_wait.parity.acquire.cta.shared::cta.b64 P1, [%0], %1, 0x989680;\n\t" \
        "@P1 bra.uni WD%=;\n\t bra.uni WL%=;\n\tWD%=:\n\t}"                      \
        :: "r"(a), "r"(ph) : "memory");                                          \
} while (0)

__device__ __forceinline__ void bulk_g2s(uint32_t dst, const void* src, uint32_t bytes, uint32_t mbar) {
    uint64_t gsrc = (uint64_t)__cvta_generic_to_global(src);
    asm volatile("cp.async.bulk.shared::cta.global.mbarrier::complete_tx::bytes [%0], [%1], %2, [%3];"
                 :: "r"(dst), "l"(gsrc), "r"(bytes), "r"(mbar) : "memory");
}

__device__ __forceinline__ void ldsm4(uint32_t& r0, uint32_t& r1, uint32_t& r2, uint32_t& r3,
                                      uint32_t addr) {
    asm volatile("ldmatrix.sync.aligned.m8n8.x4.shared.b16 {%0,%1,%2,%3}, [%4];"
                 : "=r"(r0), "=r"(r1), "=r"(r2), "=r"(r3) : "r"(addr));
}
__device__ __forceinline__ void mma_tf32(float* c, const uint32_t* a, const uint32_t* b) {
    asm volatile("mma.sync.aligned.m16n8k8.row.col.f32.tf32.tf32.f32 "
                 "{%0,%1,%2,%3}, {%4,%5,%6,%7}, {%8,%9}, {%0,%1,%2,%3};"
                 : "+f"(c[0]), "+f"(c[1]), "+f"(c[2]), "+f"(c[3])
                 : "r"(a[0]), "r"(a[1]), "r"(a[2]), "r"(a[3]), "r"(b[0]), "r"(b[1]));
}

// image layout: rows x 256B; 16B chunk c at row r lands at chunk (c ^ (r&7))
__device__ __forceinline__ uint32_t img_off(int row, int chunk) {
    return (uint32_t)row * 256u + (uint32_t)((chunk ^ (row & 7)) * 16);
}

// ----------------------------------------------------------------------------
// Kernel 1: convert k -> tf32 swizzled K-major images (32KB per 128-col tile)
// ----------------------------------------------------------------------------
__global__ __launch_bounds__(256) void convert_b_kernel(const float* __restrict__ k)
{
    int unit = blockIdx.x;
    const float* base = k + (size_t)unit * 128 * DD;
    unsigned char* dst = g_B + (size_t)unit * UNIT_BYTES;
    int tid = threadIdx.x;

    #pragma unroll
    for (int c = 0; c < 4; c++) {
        int chunk = tid + c * 256;          // 0..1023
        int row = chunk >> 3;
        int d0  = (chunk & 7) * 8;
        float4 v0 = *(const float4*)&base[row * DD + d0];
        float4 v1 = *(const float4*)&base[row * DD + d0 + 4];
        float4 o0 = make_float4(tf32r(v0.x), tf32r(v0.y), tf32r(v0.z), tf32r(v0.w));
        float4 o1 = make_float4(tf32r(v1.x), tf32r(v1.y), tf32r(v1.z), tf32r(v1.w));
        *(float4*)(dst + img_off(row, (d0 >> 2)))     = o0;
        *(float4*)(dst + img_off(row, (d0 >> 2) + 1)) = o1;
    }
}

// ----------------------------------------------------------------------------
// Kernel 2: fused tables + A-convert + TF32 HMMA GEMM + epilogue (64-row CTA)
// ----------------------------------------------------------------------------
// byte offsets (per CTA: 98.3KB -> 2 CTAs/SM)
#define AS_OFF   0                     // A image 16KB (pre-GEMM: q fp32 linear)
#define BS_OFF   16384                 // two 32KB B buffers (pre-GEMM: ew/eh)
#define QW_OFF   81920                 // 64 x pitch40 f32 = 10240
#define QH_OFF   92160                 // 64 x pitch33 f32 = 8448
#define CTRL_OFF 100608                // 4 mbarriers
#define SMEM_SZ  100672
// float-index offsets for ew/eh staging inside the B-buffer region
#define EWF  (BS_OFF / 4)              // ew: 63 rows x pitch66 (float2 stores)
#define EHF  (EWF + 4160)              // eh: 63 rows x pitch66

__global__ __launch_bounds__(288, 2) void attn_hmma_kernel(
    const float* __restrict__ q, const float* __restrict__ ew,
    const float* __restrict__ eh, float* __restrict__ out)
{
    extern __shared__ unsigned char smem[];
    float* smem_f = (float*)smem;
    const uint32_t sb = smem_u32(smem);

    const int bn = blockIdx.x >> 4;
    const int rtile = blockIdx.x & 15;           // 16 row-tiles of 64
    const int row0 = rtile * 64;
    const int n_head = bn & 7;
    const int tid = threadIdx.x, lane = tid & 31, warp = tid >> 5;
    const int warp_r = warp >> 2;     // workers: 0..1 -> 32-row group
    const int warp_c = warp & 3;      // workers: 0..3 -> 32-col strip

    const uint32_t mb0 = sb + CTRL_OFF,      mb1 = mb0 + 8;   // B-full (count 1)
    const uint32_t mc0 = mb0 + 16,           mc1 = mb0 + 24;  // B-consumed (count 8)
    if (tid == 0) {
        MBAR_INIT(mb0, 1); MBAR_INIT(mb1, 1);
        MBAR_INIT(mc0, 8); MBAR_INIT(mc1, 8);
    }

    // ---- phase A: stage q (linear, A region) + ew/eh (pitch 66, B region) ----
    if (tid < 256) {
        const float* ewb = ew + (size_t)n_head * 63 * DD;
        const float* ehb = eh + (size_t)n_head * 63 * DD;
        for (int c = tid; c < 1008; c += 256) {          // 63 rows x 16 float4
            int row = c >> 4, d0 = (c & 15) * 4;
            float4 vw = *(const float4*)&ewb[row * DD + d0];
            float4 vh = *(const float4*)&ehb[row * DD + d0];
            float* dw = &smem_f[EWF + row * 66 + d0];
            float* dh = &smem_f[EHF + row * 66 + d0];
            *(float2*)(dw + 0) = make_float2(vw.x, vw.y);
            *(float2*)(dw + 2) = make_float2(vw.z, vw.w);
            *(float2*)(dh + 0) = make_float2(vh.x, vh.y);
            *(float2*)(dh + 2) = make_float2(vh.z, vh.w);
        }
        const float* qb = q + ((size_t)bn * LQ + row0) * DD;
        #pragma unroll
        for (int it = 0; it < 4; it++) {                 // 64 rows x 16 float4
            int c = tid + it * 256;
            int row = c >> 4, d0 = (c & 15) * 4;
            *(float4*)&smem_f[row * 64 + d0] = *(const float4*)&qb[(size_t)row * DD + d0];
        }
    }
    __syncthreads();   // S1

    // ---- phase B: exact fp32 qw/qh windows + qreg read ----
    float* qw_s = smem_f + QW_OFF / 4;   // [row][y] pitch 40 (64 rows)
    float* qh_s = smem_f + QH_OFF / 4;   // [row][x] pitch 33 (64 rows)
    if (warp < 8) {
        #pragma unroll 1
        for (int pass = 0; pass < 16; pass++) {
            int task = warp * 16 + pass;                  // 0..127
            bool isW = task < 64;
            int r = isW ? task : task - 64;               // local row 0..63
            int shift = isW ? (31 - (r & 31)) : (31 - (rtile * 2 + (r >> 5)));
            const float* erow = smem_f + (isW ? EWF : EHF) + (size_t)(shift + lane) * 66;
            const float* qrow = smem_f + (size_t)r * 64;
            ull acc = 0;
            #pragma unroll 8
            for (int kk = 0; kk < 32; kk++) {
                ull qp = *(const ull*)(qrow + 2 * kk);    // broadcast
                ull ep = *(const ull*)(erow + 2 * kk);
                ffma2(acc, qp, ep);
            }
            float vlo, vhi; unpack2(acc, vlo, vhi);
            float v = vlo + vhi;
            if (isW) qw_s[r * 40 + lane] = v;
            else     qh_s[r * 33 + lane] = v;
        }
    }
    // read q chunks this thread will rewrite swizzled (64 rows x 8 chunks = 512)
    float qreg[2][8];
    if (tid < 256) {
        #pragma unroll
        for (int c = 0; c < 2; c++) {
            int chunk = tid + c * 256;
            int row = chunk >> 3, d0 = (chunk & 7) * 8;
            float4 v0 = *(const float4*)&smem_f[row * 64 + d0];
            float4 v1 = *(const float4*)&smem_f[row * 64 + d0 + 4];
            qreg[c][0] = v0.x; qreg[c][1] = v0.y; qreg[c][2] = v0.z; qreg[c][3] = v0.w;
            qreg[c][4] = v1.x; qreg[c][5] = v1.y; qreg[c][6] = v1.z; qreg[c][7] = v1.w;
        }
    }
    __syncthreads();   // S2: q/e reads done; tables written; B region free

    // producer prologue: fill both B buffers (overlaps phase C below)
    if (warp == 8 && elect_one()) {
        asm volatile("fence.proxy.async.shared::cta;" ::: "memory");
        MBAR_EXPECT_TX(mb0, UNIT_BYTES);
        bulk_g2s(sb + BS_OFF, g_B + (size_t)(bn * 8) * UNIT_BYTES, UNIT_BYTES, mb0);
        MBAR_EXPECT_TX(mb1, UNIT_BYTES);
        bulk_g2s(sb + BS_OFF + UNIT_BYTES, g_B + (size_t)(bn * 8 + 1) * UNIT_BYTES,
                 UNIT_BYTES, mb1);
    }

    // ---- phase C: write swizzled tf32 A image in place (64 rows, 16KB) ----
    if (tid < 256) {
        #pragma unroll
        for (int c = 0; c < 2; c++) {
            int chunk = tid + c * 256;
            int row = chunk >> 3, d0 = (chunk & 7) * 8;
            float4 o0 = make_float4(tf32r(qreg[c][0]), tf32r(qreg[c][1]),
                                    tf32r(qreg[c][2]), tf32r(qreg[c][3]));
            float4 o1 = make_float4(tf32r(qreg[c][4]), tf32r(qreg[c][5]),
                                    tf32r(qreg[c][6]), tf32r(qreg[c][7]));
            *(float4*)(smem + AS_OFF + img_off(row, (d0 >> 2)))     = o0;
            *(float4*)(smem + AS_OFF + img_off(row, (d0 >> 2) + 1)) = o1;
        }
    }
    __syncthreads();   // S3: A image ready

    // lane decomposition for ldmatrix addressing (f32 8x4 blocks as b16 m8n8)
    const int r8 = lane & 7;
    const int ma = (lane >> 3) & 1, ka = lane >> 4;       // A: row-half, chunk-half
    const int gb = lane >> 4,       cb = (lane >> 3) & 1; // B: n-group, chunk-half
    const uint32_t a_base = sb + AS_OFF + (uint32_t)(warp_r * 32 + ma * 8 + r8) * 256;
    const uint32_t b_off  = (uint32_t)(warp_c * 32 + gb * 8 + r8) * 256;

    // epilogue lane mapping
    const int l4 = lane >> 2, l2 = (lane & 3) * 2;
    float* outb = out + ((size_t)bn << 20);

    if (warp < 8) {
        #pragma unroll 1
        for (int ct = 0; ct < 8; ct++) {
            const int buf = ct & 1;
            MBAR_WAIT(buf ? mb1 : mb0, (ct >> 1) & 1);
            const uint32_t b_base = sb + BS_OFF + (uint32_t)buf * UNIT_BYTES + b_off;

            float acc[2][4][4];
            #pragma unroll
            for (int mt = 0; mt < 2; mt++)
                #pragma unroll
                for (int nn = 0; nn < 4; nn++)
                    #pragma unroll
                    for (int e = 0; e < 4; e++) acc[mt][nn][e] = 0.f;

            #pragma unroll
            for (int s = 0; s < 8; s++) {
                uint32_t af[2][4];
                const uint32_t ca = (uint32_t)(((2 * s + ka) ^ r8) * 16);
                #pragma unroll
                for (int mt = 0; mt < 2; mt++)
                    ldsm4(af[mt][0], af[mt][1], af[mt][2], af[mt][3],
                          a_base + (uint32_t)(mt * 16 * 256) + ca);
                uint32_t bf[2][4];
                const uint32_t cbb = (uint32_t)(((2 * s + cb) ^ r8) * 16);
                #pragma unroll
                for (int np = 0; np < 2; np++)
                    ldsm4(bf[np][0], bf[np][1], bf[np][2], bf[np][3],
                          b_base + (uint32_t)(np * 16 * 256) + cbb);
                #pragma unroll
                for (int mt = 0; mt < 2; mt++)
                    #pragma unroll
                    for (int nn = 0; nn < 4; nn++)
                        mma_tf32(acc[mt][nn], af[mt], &bf[nn >> 1][(nn & 1) * 2]);
            }

            // all B ldsm of this tile complete -> release the buffer
            if (elect_one()) MBAR_ARRIVE(buf ? mc1 : mc0);

            // epilogue (no CTA barrier): qw/qh from smem, STG.64
            const int xq = ct * 4 + warp_c;               // warp-uniform x index
            #pragma unroll
            for (int mt = 0; mt < 2; mt++) {
                #pragma unroll
                for (int half = 0; half < 2; half++) {
                    const int r = warp_r * 32 + mt * 16 + half * 8 + l4;  // 0..63
                    const float hv = qh_s[r * 33 + xq];
                    float* op = outb + (size_t)(row0 + r) * 1024
                              + ct * 128 + warp_c * 32 + l2;
                    #pragma unroll
                    for (int nn = 0; nn < 4; nn++) {
                        float2 wv = *(const float2*)&qw_s[r * 40 + nn * 8 + l2];
                        float2 o;
                        o.x = acc[mt][nn][half * 2 + 0] + wv.x + hv;
                        o.y = acc[mt][nn][half * 2 + 1] + wv.y + hv;
                        *(float2*)(op + nn * 8) = o;
                    }
                }
            }
        }
    } else if (warp == 8) {
        // ---- producer: tiles 2..7 (double buffer, waits consumed[t-2]) ----
        if (elect_one()) {
            #pragma unroll 1
            for (int t = 2; t < 8; t++) {
                const int b = t & 1;
                MBAR_WAIT(b ? mc1 : mc0, ((t - 2) >> 1) & 1);
                MBAR_EXPECT_TX(b ? mb1 : mb0, UNIT_BYTES);
                bulk_g2s(sb + BS_OFF + (uint32_t)b * UNIT_BYTES,
                         g_B + ((size_t)bn * 8 + t) * UNIT_BYTES, UNIT_BYTES,
                         b ? mb1 : mb0);
            }
        }
    }
}

// ----------------------------------------------------------------------------
extern "C" void kernel_launch(void* const* d_in, const int* in_sizes, int n_in,
                              void* d_out, int out_size)
{
    const float* q  = (const float*)d_in[0];
    const float* k  = (const float*)d_in[1];
    const float* ew = (const float*)d_in[2];
    const float* eh = (const float*)d_in[3];
    float* out = (float*)d_out;

    cudaFuncSetAttribute(attn_hmma_kernel, cudaFuncAttributeMaxDynamicSharedMemorySize, SMEM_SZ);

    convert_b_kernel<<<512, 256>>>(k);
    attn_hmma_kernel<<<1024, 288, SMEM_SZ>>>(q, ew, eh, out);
}